// round 16
// baseline (speedup 1.0000x reference)
#include <cuda_runtime.h>
#include <cuda_bf16.h>
#include <cstdint>

#define L_ 1024
#define B_ 8
#define E_ 512
#define H_ 8
#define D_ 64
#define ROWS_ (L_*B_)          /* 8192 */
#define QKV_LD (3*E_)          /* 1536 */

// ---------------- scratch (no cudaMalloc allowed) ----------------
__device__ __nv_bfloat16 g_qkvh[(size_t)ROWS_ * QKV_LD];
__device__ __nv_bfloat16 g_qkvl[(size_t)ROWS_ * QKV_LD];
__device__ __nv_bfloat16 g_atth[(size_t)ROWS_ * E_];
__device__ __nv_bfloat16 g_attl[(size_t)ROWS_ * E_];
__device__ __nv_bfloat16 g_xh[(size_t)ROWS_ * E_];
__device__ __nv_bfloat16 g_xl[(size_t)ROWS_ * E_];
__device__ __nv_bfloat16 g_iwh[(size_t)QKV_LD * E_];
__device__ __nv_bfloat16 g_iwl[(size_t)QKV_LD * E_];
__device__ __nv_bfloat16 g_owh[(size_t)E_ * E_];
__device__ __nv_bfloat16 g_owl[(size_t)E_ * E_];
__device__ unsigned char g_edge8[(size_t)B_ * L_ * L_];
__device__ int g_is64;
__device__ int g_mask_nz;

// ================= helpers (plain sm_103-safe) =================
__device__ __forceinline__ uint32_t cvta_smem(const void* p) {
    uint32_t a;
    asm("{ .reg .u64 t; cvta.to.shared.u64 t, %1; cvt.u32.u64 %0, t; }" : "=r"(a) : "l"(p));
    return a;
}
__device__ __forceinline__ void ldsm4(uint32_t& r0, uint32_t& r1, uint32_t& r2, uint32_t& r3, uint32_t a) {
    asm volatile("ldmatrix.sync.aligned.m8n8.x4.shared.b16 {%0,%1,%2,%3}, [%4];"
                 : "=r"(r0), "=r"(r1), "=r"(r2), "=r"(r3) : "r"(a));
}
__device__ __forceinline__ void ldsm4t(uint32_t& r0, uint32_t& r1, uint32_t& r2, uint32_t& r3, uint32_t a) {
    asm volatile("ldmatrix.sync.aligned.m8n8.x4.trans.shared.b16 {%0,%1,%2,%3}, [%4];"
                 : "=r"(r0), "=r"(r1), "=r"(r2), "=r"(r3) : "r"(a));
}
__device__ __forceinline__ void mma_bf16(float& d0, float& d1, float& d2, float& d3,
                                         uint32_t a0, uint32_t a1, uint32_t a2, uint32_t a3,
                                         uint32_t b0, uint32_t b1) {
    asm volatile("mma.sync.aligned.m16n8k16.row.col.f32.bf16.bf16.f32 "
                 "{%0,%1,%2,%3}, {%4,%5,%6,%7}, {%8,%9}, {%0,%1,%2,%3};"
                 : "+f"(d0), "+f"(d1), "+f"(d2), "+f"(d3)
                 : "r"(a0), "r"(a1), "r"(a2), "r"(a3), "r"(b0), "r"(b1));
}
#define CP_ASYNC16(dst, src) \
    asm volatile("cp.async.cg.shared.global [%0], [%1], 16;" :: "r"((uint32_t)(dst)), "l"(src))
#define CP_COMMIT() asm volatile("cp.async.commit_group;" ::: "memory")
#define CP_WAIT0()  asm volatile("cp.async.wait_group 0;" ::: "memory")
#define CP_WAIT1()  asm volatile("cp.async.wait_group 1;" ::: "memory")

// fast fp32-pair -> packed bf16x2 (RN, identical numerics to __float2bfloat16)
__device__ __forceinline__ uint32_t cvt_bf16x2(float lo, float hi) {
    uint32_t r;
    asm("cvt.rn.bf16x2.f32 %0, %1, %2;" : "=r"(r) : "f"(hi), "f"(lo));
    return r;
}
__device__ __forceinline__ void split2(float x, float y, uint32_t& hi, uint32_t& lo) {
    hi = cvt_bf16x2(x, y);
    const float xr = __uint_as_float(hi << 16);
    const float yr = __uint_as_float(hi & 0xFFFF0000u);
    lo = cvt_bf16x2(x - xr, y - yr);
}
__device__ __forceinline__ void split4(const float4 v, uint2& hi, uint2& lo) {
    split2(v.x, v.y, hi.x, lo.x);
    split2(v.z, v.w, hi.y, lo.y);
}

// ---------------- detect edge dtype + zero mask flag ----------------
__global__ void detect_edge_dtype_kernel(const unsigned int* __restrict__ e)
{
    const int t = threadIdx.x;
    unsigned v = 0;
    for (int i = t; i < 512; i += 32) v |= e[2 * i + 1];
    const unsigned any = __ballot_sync(0xffffffffu, v != 0u);
    if (t == 0) { g_is64 = (any == 0u) ? 1 : 0; g_mask_nz = 0; }
}

// ---------------- scan attn_mask for any nonzero ----------------
__global__ __launch_bounds__(256) void scan_mask_kernel(const float* __restrict__ m)
{
    const int i = (blockIdx.x * 256 + threadIdx.x) * 8;
    const uint4 a = *(const uint4*)(m + i);
    const uint4 b = *(const uint4*)(m + i + 4);
    const unsigned v = a.x | a.y | a.z | a.w | b.x | b.y | b.z | b.w;
    const unsigned any = __ballot_sync(0xffffffffu, v != 0u);
    if ((threadIdx.x & 31) == 0 && any) atomicOr(&g_mask_nz, 1);
}

// ---------------- pack edge (int32 or int64) -> uint8 ----------------
__global__ __launch_bounds__(256) void pack_edge_kernel(const void* __restrict__ edge)
{
    const int i = blockIdx.x * blockDim.x + threadIdx.x;
    uchar4 u;
    if (g_is64) {
        const long long* e = (const long long*)edge;
        u.x = (unsigned char)e[(size_t)i*4 + 0];
        u.y = (unsigned char)e[(size_t)i*4 + 1];
        u.z = (unsigned char)e[(size_t)i*4 + 2];
        u.w = (unsigned char)e[(size_t)i*4 + 3];
    } else {
        const int4 v = *(const int4*)((const int*)edge + (size_t)i*4);
        u.x = (unsigned char)v.x; u.y = (unsigned char)v.y;
        u.z = (unsigned char)v.z; u.w = (unsigned char)v.w;
    }
    *(uchar4*)(g_edge8 + (size_t)i*4) = u;
}

// ---------------- fp32 -> bf16 hi/lo splitter ----------------
__global__ __launch_bounds__(256) void split_kernel(
    const float* __restrict__ src, __nv_bfloat16* __restrict__ hi,
    __nv_bfloat16* __restrict__ lo, int n4)
{
    const int i = blockIdx.x * blockDim.x + threadIdx.x;
    if (i >= n4) return;
    uint2 h, l;
    split4(*(const float4*)(src + (size_t)i * 4), h, l);
    *(uint2*)(hi + (size_t)i * 4) = h;
    *(uint2*)(lo + (size_t)i * 4) = l;
}

// ================= HMMA GEMM (unchanged from R9) =================
#define GP 40
#define GTILE (128*GP*2)
#define GSTG  (4*GTILE)
#define GEMM_SMEM (2*GSTG)

__global__ __launch_bounds__(256, 2) void gemm_bf16(
    const __nv_bfloat16* __restrict__ Ah, const __nv_bfloat16* __restrict__ Al,
    const __nv_bfloat16* __restrict__ Bh, const __nv_bfloat16* __restrict__ Bl,
    const float* __restrict__ bias,
    float* __restrict__ Cf, __nv_bfloat16* __restrict__ Ch, __nv_bfloat16* __restrict__ Cl,
    int N, int K, int split_out)
{
    extern __shared__ char smc[];
    const uint32_t sb = cvta_smem(smc);
    const int t = threadIdx.x, wid = t >> 5, lane = t & 31;
    const int wm = wid & 3, wn = wid >> 2;
    const int bm = blockIdx.y << 7, bn = blockIdx.x << 7;

    const int r = t >> 1, half = t & 1;
    const __nv_bfloat16* a_h = Ah + (size_t)(bm + r) * K + half * 16;
    const __nv_bfloat16* a_l = Al + (size_t)(bm + r) * K + half * 16;
    const __nv_bfloat16* b_h = Bh + (size_t)(bn + r) * K + half * 16;
    const __nv_bfloat16* b_l = Bl + (size_t)(bn + r) * K + half * 16;
    const uint32_t dstb = (uint32_t)(r * (GP*2) + half * 32);

    const int niter = K >> 5;
#pragma unroll
    for (int p = 0; p < 2; p++) {
        const uint32_t d = sb + p * GSTG + dstb;
        const int ko = p * 32;
        CP_ASYNC16(d,             a_h + ko); CP_ASYNC16(d + 16,             a_h + ko + 8);
        CP_ASYNC16(d + GTILE,     a_l + ko); CP_ASYNC16(d + GTILE + 16,     a_l + ko + 8);
        CP_ASYNC16(d + 2*GTILE,   b_h + ko); CP_ASYNC16(d + 2*GTILE + 16,   b_h + ko + 8);
        CP_ASYNC16(d + 3*GTILE,   b_l + ko); CP_ASYNC16(d + 3*GTILE + 16,   b_l + ko + 8);
        CP_COMMIT();
    }

    float acc[2][8][4];
#pragma unroll
    for (int i = 0; i < 2; i++)
#pragma unroll
        for (int j = 0; j < 8; j++)
#pragma unroll
            for (int c = 0; c < 4; c++) acc[i][j][c] = 0.f;

    const uint32_t a_row = (uint32_t)((lane & 7) + ((lane >> 3) & 1) * 8);
    const uint32_t a_kb  = (uint32_t)((lane >> 4) << 4);
    const uint32_t p_row = (uint32_t)((lane & 7) + ((lane >> 4) & 1) * 8);
    const uint32_t p_kb  = (uint32_t)(((lane >> 3) & 1) << 4);

    for (int it = 0; it < niter; it++) {
        if (it == niter - 1) { CP_WAIT0(); } else { CP_WAIT1(); }
        __syncthreads();
        const uint32_t s = sb + (uint32_t)((it & 1) * GSTG);
#pragma unroll
        for (int kk = 0; kk < 2; kk++) {
            uint32_t ah[2][4], al[2][4];
#pragma unroll
            for (int i = 0; i < 2; i++) {
                const uint32_t ad = s + (uint32_t)(wm * 32 + i * 16 + a_row) * (GP*2)
                                  + (uint32_t)(kk * 32) + a_kb;
                ldsm4(ah[i][0], ah[i][1], ah[i][2], ah[i][3], ad);
                ldsm4(al[i][0], al[i][1], al[i][2], al[i][3], ad + GTILE);
            }
#pragma unroll
            for (int jp = 0; jp < 4; jp++) {
                const uint32_t bd = s + 2*GTILE + (uint32_t)(wn * 64 + jp * 16 + p_row) * (GP*2)
                                  + (uint32_t)(kk * 32) + p_kb;
                uint32_t bh0, bh1, bh2, bh3, bl0, bl1, bl2, bl3;
                ldsm4(bh0, bh1, bh2, bh3, bd);
                ldsm4(bl0, bl1, bl2, bl3, bd + GTILE);
                float* x00 = acc[0][2*jp]; float* x01 = acc[0][2*jp+1];
                float* x10 = acc[1][2*jp]; float* x11 = acc[1][2*jp+1];
                mma_bf16(x00[0], x00[1], x00[2], x00[3], ah[0][0], ah[0][1], ah[0][2], ah[0][3], bh0, bh1);
                mma_bf16(x01[0], x01[1], x01[2], x01[3], ah[0][0], ah[0][1], ah[0][2], ah[0][3], bh2, bh3);
                mma_bf16(x10[0], x10[1], x10[2], x10[3], ah[1][0], ah[1][1], ah[1][2], ah[1][3], bh0, bh1);
                mma_bf16(x11[0], x11[1], x11[2], x11[3], ah[1][0], ah[1][1], ah[1][2], ah[1][3], bh2, bh3);
                mma_bf16(x00[0], x00[1], x00[2], x00[3], ah[0][0], ah[0][1], ah[0][2], ah[0][3], bl0, bl1);
                mma_bf16(x01[0], x01[1], x01[2], x01[3], ah[0][0], ah[0][1], ah[0][2], ah[0][3], bl2, bl3);
                mma_bf16(x10[0], x10[1], x10[2], x10[3], ah[1][0], ah[1][1], ah[1][2], ah[1][3], bl0, bl1);
                mma_bf16(x11[0], x11[1], x11[2], x11[3], ah[1][0], ah[1][1], ah[1][2], ah[1][3], bl2, bl3);
                mma_bf16(x00[0], x00[1], x00[2], x00[3], al[0][0], al[0][1], al[0][2], al[0][3], bh0, bh1);
                mma_bf16(x01[0], x01[1], x01[2], x01[3], al[0][0], al[0][1], al[0][2], al[0][3], bh2, bh3);
                mma_bf16(x10[0], x10[1], x10[2], x10[3], al[1][0], al[1][1], al[1][2], al[1][3], bh0, bh1);
                mma_bf16(x11[0], x11[1], x11[2], x11[3], al[1][0], al[1][1], al[1][2], al[1][3], bh2, bh3);
            }
        }
        __syncthreads();
        if (it + 2 < niter) {
            const uint32_t d = sb + ((it + 2) & 1) * GSTG + dstb;
            const int ko = (it + 2) * 32;
            CP_ASYNC16(d,             a_h + ko); CP_ASYNC16(d + 16,             a_h + ko + 8);
            CP_ASYNC16(d + GTILE,     a_l + ko); CP_ASYNC16(d + GTILE + 16,     a_l + ko + 8);
            CP_ASYNC16(d + 2*GTILE,   b_h + ko); CP_ASYNC16(d + 2*GTILE + 16,   b_h + ko + 8);
            CP_ASYNC16(d + 3*GTILE,   b_l + ko); CP_ASYNC16(d + 3*GTILE + 16,   b_l + ko + 8);
            CP_COMMIT();
        }
    }

#pragma unroll
    for (int i = 0; i < 2; i++) {
        const int r0 = bm + wm * 32 + i * 16 + (lane >> 2);
#pragma unroll
        for (int j = 0; j < 8; j++) {
            const int c = bn + wn * 64 + j * 8 + (lane & 3) * 2;
            const float2 b2 = *(const float2*)(bias + c);
            const float v00 = acc[i][j][0] + b2.x, v01 = acc[i][j][1] + b2.y;
            const float v10 = acc[i][j][2] + b2.x, v11 = acc[i][j][3] + b2.y;
            if (split_out) {
                uint32_t h0, l0v, h1, l1v;
                split2(v00, v01, h0, l0v);
                split2(v10, v11, h1, l1v);
                *(uint32_t*)(Ch + (size_t)r0 * N + c)       = h0;
                *(uint32_t*)(Cl + (size_t)r0 * N + c)       = l0v;
                *(uint32_t*)(Ch + (size_t)(r0 + 8) * N + c) = h1;
                *(uint32_t*)(Cl + (size_t)(r0 + 8) * N + c) = l1v;
            } else {
                float2 o0 = { v00, v01 }, o1 = { v10, v11 };
                *(float2*)(Cf + (size_t)r0 * N + c)       = o0;
                *(float2*)(Cf + (size_t)(r0 + 8) * N + c) = o1;
            }
        }
    }
}

// ================= HMMA fused flash attention (all tiles double-buffered) =================
// grid (8, 64), 256 thr = 8 warps. K, V, edge double-buffered, one commit
// group per iteration (prefetch distance 1), 2 barriers/iter, no mid waits.
// Mask: skipped entirely when g_mask_nz == 0 (direct-LDG slow path otherwise).
#define KVP 144                          /* bytes per K/V row (72 bf16) */
#define KBUF 18432                       /* per K or V buffer (hi+lo) */
#define K0_OFF 0
#define K1_OFF 18432
#define V0_OFF 36864
#define V1_OFF 55296
#define EDGEP 80
#define E0_OFF 73728                     /* 128*80 = 10240 per buffer */
#define E1_OFF 83968
#define KPS_OFF 94208
#define ATTN_SMEM (KPS_OFF + 4096 + 64)  /* ~98.4 KB -> 2 CTAs/SM */

__global__ __launch_bounds__(256, 2) void attn_hmma(
    const float* __restrict__ attn_mask,
    const unsigned char* __restrict__ kpm,
    const float* __restrict__ edge_tab)
{
    extern __shared__ char smc[];
    const uint32_t sb = cvta_smem(smc);

    const int t = threadIdx.x, w = t >> 5, lane = t & 31;
    const int qb = blockIdx.x, bh = blockIdx.y;
    const int b = bh >> 3, h = bh & 7;
    const int q0 = qb << 7;
    const size_t edge_base = (size_t)b << 20;
    const int mnz = g_mask_nz;

    const float etreg = edge_tab[(lane & 15) * H_ + h];

    const uint32_t a_row = (uint32_t)((lane & 7) + ((lane >> 3) & 1) * 8);
    const uint32_t a_kb  = (uint32_t)((lane >> 4) << 4);
    const uint32_t p_row = (uint32_t)((lane & 7) + ((lane >> 4) & 1) * 8);
    const uint32_t p_kb  = (uint32_t)(((lane >> 3) & 1) << 4);
    const uint32_t v_row = (uint32_t)(lane & 15);
    const uint32_t v_cb  = (uint32_t)((lane >> 4) << 4);

    const int kv_r = t >> 2, kv_q4 = t & 3;
    const uint32_t kv_d = (uint32_t)(kv_r * KVP + kv_q4 * 32);
    const int me_i = t >> 1, me_half = t & 1;

    // ---- prologue: kps table + Q staging (through K0/K1 regions) ----
    {
        const uchar4 kc = *(const uchar4*)(kpm + b * L_ + t * 4);
        float4 kf;
        kf.x = kc.x ? -1e30f : 0.f; kf.y = kc.y ? -1e30f : 0.f;
        kf.z = kc.z ? -1e30f : 0.f; kf.w = kc.w ? -1e30f : 0.f;
        *(float4*)(smc + KPS_OFF + t * 16) = kf;
    }
    {
        const __nv_bfloat16* qh = g_qkvh + (size_t)((q0 + me_i) * B_ + b) * QKV_LD + h * D_ + me_half * 32;
        const __nv_bfloat16* ql = g_qkvl + (size_t)((q0 + me_i) * B_ + b) * QKV_LD + h * D_ + me_half * 32;
        const uint32_t d = sb + (uint32_t)(me_i * KVP + me_half * 64);
#pragma unroll
        for (int g = 0; g < 4; g++) {
            CP_ASYNC16(d + g * 16,          qh + g * 8);
            CP_ASYNC16(d + K1_OFF + g * 16, ql + g * 8);
        }
        CP_COMMIT();
        CP_WAIT0();
    }
    __syncthreads();
    uint32_t qfh[4][4], qfl[4][4];
#pragma unroll
    for (int kk = 0; kk < 4; kk++) {
        const uint32_t qa = sb + (uint32_t)(w * 16 + a_row) * KVP + (uint32_t)(kk * 32) + a_kb;
        ldsm4(qfh[kk][0], qfh[kk][1], qfh[kk][2], qfh[kk][3], qa);
        ldsm4(qfl[kk][0], qfl[kk][1], qfl[kk][2], qfl[kk][3], qa + K1_OFF);
    }
    __syncthreads();   // all warps done reading Q region before K/V overwrite

    // issue group(0): K(0), V(0), edge(0) into buffers 0
    {
        const size_t rowb = (size_t)((0 + kv_r) * B_ + b) * QKV_LD + h * D_;
        const __nv_bfloat16* kh = g_qkvh + rowb + E_   + kv_q4 * 16;
        const __nv_bfloat16* kl = g_qkvl + rowb + E_   + kv_q4 * 16;
        const __nv_bfloat16* vh = g_qkvh + rowb + 2*E_ + kv_q4 * 16;
        const __nv_bfloat16* vl = g_qkvl + rowb + 2*E_ + kv_q4 * 16;
        const uint32_t dk = sb + K0_OFF + kv_d;
        const uint32_t dv = sb + V0_OFF + kv_d;
        CP_ASYNC16(dk,        kh); CP_ASYNC16(dk + 16,        kh + 8);
        CP_ASYNC16(dk + 9216, kl); CP_ASYNC16(dk + 9216 + 16, kl + 8);
        CP_ASYNC16(dv,        vh); CP_ASYNC16(dv + 16,        vh + 8);
        CP_ASYNC16(dv + 9216, vl); CP_ASYNC16(dv + 9216 + 16, vl + 8);
        const unsigned char* esrc = g_edge8 + edge_base + (size_t)(q0 + me_i) * L_ + me_half * 32;
        const uint32_t ed = sb + E0_OFF + (uint32_t)(me_i * EDGEP + me_half * 32);
        CP_ASYNC16(ed, esrc); CP_ASYNC16(ed + 16, esrc + 16);
        CP_COMMIT();
    }

    float o[8][4];
#pragma unroll
    for (int j = 0; j < 8; j++)
#pragma unroll
        for (int c = 0; c < 4; c++) o[j][c] = 0.f;
    float m0p = -1e30f, m1p = -1e30f, l0 = 0.f, l1 = 0.f;

    for (int kb = 0; kb < 16; kb++) {
        const int m0 = kb << 6;
        if (kb) __syncthreads();   // (A) all warps done with buffers we overwrite next

        // ---- issue group(kb+1) into alt buffers ----
        if (kb + 1 < 16) {
            const int alt = (kb + 1) & 1;
            const size_t rowb = (size_t)(((m0 + 64) + kv_r) * B_ + b) * QKV_LD + h * D_;
            const __nv_bfloat16* kh = g_qkvh + rowb + E_   + kv_q4 * 16;
            const __nv_bfloat16* kl = g_qkvl + rowb + E_   + kv_q4 * 16;
            const __nv_bfloat16* vh = g_qkvh + rowb + 2*E_ + kv_q4 * 16;
            const __nv_bfloat16* vl = g_qkvl + rowb + 2*E_ + kv_q4 * 16;
            const uint32_t dk = sb + (uint32_t)(alt ? K1_OFF : K0_OFF) + kv_d;
            const uint32_t dv = sb + (uint32_t)(alt ? V1_OFF : V0_OFF) + kv_d;
            CP_ASYNC16(dk,        kh); CP_ASYNC16(dk + 16,        kh + 8);
            CP_ASYNC16(dk + 9216, kl); CP_ASYNC16(dk + 9216 + 16, kl + 8);
            CP_ASYNC16(dv,        vh); CP_ASYNC16(dv + 16,        vh + 8);
            CP_ASYNC16(dv + 9216, vl); CP_ASYNC16(dv + 9216 + 16, vl + 8);
            const unsigned char* esrc = g_edge8 + edge_base + (size_t)(q0 + me_i) * L_ + (m0 + 64) + me_half * 32;
            const uint32_t ed = sb + (uint32_t)(alt ? E1_OFF : E0_OFF) + (uint32_t)(me_i * EDGEP + me_half * 32);
            CP_ASYNC16(ed, esrc); CP_ASYNC16(ed + 16, esrc + 16);
            CP_COMMIT();
            CP_WAIT1();            // group(kb) complete
        } else {
            CP_WAIT0();
        }
        __syncthreads();           // (C) group(kb) visible to all warps

        const int cur = kb & 1;
        const uint32_t kbuf = sb + (uint32_t)(cur ? K1_OFF : K0_OFF);
        const uint32_t vbuf = sb + (uint32_t)(cur ? V1_OFF : V0_OFF);
        const uint32_t ebuf = (uint32_t)(cur ? E1_OFF : E0_OFF);

        // ---- S = Q K^T (16 x 64 per warp), 3 products, interleaved ----
        float sacc[8][4];
#pragma unroll
        for (int j = 0; j < 8; j++)
#pragma unroll
            for (int c = 0; c < 4; c++) sacc[j][c] = 0.f;
#pragma unroll
        for (int kk = 0; kk < 4; kk++) {
#pragma unroll
            for (int jp = 0; jp < 4; jp++) {
                const uint32_t ka = kbuf + (uint32_t)(jp * 16 + p_row) * KVP
                                  + (uint32_t)(kk * 32) + p_kb;
                uint32_t kh0, kh1, kh2, kh3, kl0, kl1, kl2, kl3;
                ldsm4(kh0, kh1, kh2, kh3, ka);
                ldsm4(kl0, kl1, kl2, kl3, ka + 9216);
                float* s0 = sacc[2*jp];
                float* s1 = sacc[2*jp+1];
                mma_bf16(s0[0], s0[1], s0[2], s0[3], qfh[kk][0], qfh[kk][1], qfh[kk][2], qfh[kk][3], kh0, kh1);
                mma_bf16(s1[0], s1[1], s1[2], s1[3], qfh[kk][0], qfh[kk][1], qfh[kk][2], qfh[kk][3], kh2, kh3);
                mma_bf16(s0[0], s0[1], s0[2], s0[3], qfh[kk][0], qfh[kk][1], qfh[kk][2], qfh[kk][3], kl0, kl1);
                mma_bf16(s1[0], s1[1], s1[2], s1[3], qfh[kk][0], qfh[kk][1], qfh[kk][2], qfh[kk][3], kl2, kl3);
                mma_bf16(s0[0], s0[1], s0[2], s0[3], qfl[kk][0], qfl[kk][1], qfl[kk][2], qfl[kk][3], kh0, kh1);
                mma_bf16(s1[0], s1[1], s1[2], s1[3], qfl[kk][0], qfl[kk][1], qfl[kk][2], qfl[kk][3], kh2, kh3);
            }
        }

        // ---- S epilogue: scale + edge(shfl) + kps (+ mask LDG slow path) ----
        {
            const int rl = w * 16 + (lane >> 2);
            const uint32_t erow0 = ebuf + (uint32_t)(rl * EDGEP);
#pragma unroll
            for (int j = 0; j < 8; j++) {
                const int c = j * 8 + (lane & 3) * 2;
                const float2 kp = *(const float2*)(smc + KPS_OFF + (m0 + c) * 4);
                const unsigned short e0 = *(const unsigned short*)(smc + erow0 + c);
                const unsigned short e1 = *(const unsigned short*)(smc + erow0 + 8 * EDGEP + c);
                const float ev00 = __shfl_sync(0xffffffffu, etreg, e0 & 15);
                const float ev01 = __shfl_sync(0xffffffffu, etreg, (e0 >> 8) & 15);
                const float ev10 = __shfl_sync(0xffffffffu, etreg, e1 & 15);
                const float ev11 = __shfl_sync(0xffffffffu, etreg, (e1 >> 8) & 15);
                float mk00 = 0.f, mk01 = 0.f, mk10 = 0.f, mk11 = 0.f;
                if (mnz) {   // slow path: direct LDG of mask (L2-cached)
                    const float2 m0v = *(const float2*)(attn_mask + (size_t)(q0 + rl) * L_ + m0 + c);
                    const float2 m1v = *(const float2*)(attn_mask + (size_t)(q0 + rl + 8) * L_ + m0 + c);
                    mk00 = m0v.x; mk01 = m0v.y; mk10 = m1v.x; mk11 = m1v.y;
                }
                sacc[j][0] = sacc[j][0] * 0.125f + mk00 + ev00 + kp.x;
                sacc[j][1] = sacc[j][1] * 0.125f + mk01 + ev01 + kp.y;
                sacc[j][2] = sacc[j][2] * 0.125f + mk10 + ev10 + kp.x;
                sacc[j][3] = sacc[j][3] * 0.125f + mk11 + ev11 + kp.y;
            }
        }

        // ---- online softmax ----
        float mx0 = -1e30f, mx1 = -1e30f;
#pragma unroll
        for (int j = 0; j < 8; j++) {
            mx0 = fmaxf(mx0, fmaxf(sacc[j][0], sacc[j][1]));
            mx1 = fmaxf(mx1, fmaxf(sacc[j][2], sacc[j][3]));
        }
        mx0 = fmaxf(mx0, __shfl_xor_sync(0xffffffffu, mx0, 1));
        mx0 = fmaxf(mx0, __shfl_xor_sync(0xffffffffu, mx0, 2));
        mx1 = fmaxf(mx1, __shfl_xor_sync(0xffffffffu, mx1, 1));
        mx1 = fmaxf(mx1, __shfl_xor_sync(0xffffffffu, mx1, 2));
        const float mn0 = fmaxf(m0p, mx0), mn1 = fmaxf(m1p, mx1);
        const float c0 = __expf(m0p - mn0), c1 = __expf(m1p - mn1);
        m0p = mn0; m1p = mn1;
        float s0 = 0.f, s1 = 0.f;
#pragma unroll
        for (int j = 0; j < 8; j++) {
            sacc[j][0] = __expf(sacc[j][0] - mn0); s0 += sacc[j][0];
            sacc[j][1] = __expf(sacc[j][1] - mn0); s0 += sacc[j][1];
            sacc[j][2] = __expf(sacc[j][2] - mn1); s1 += sacc[j][2];
            sacc[j][3] = __expf(sacc[j][3] - mn1); s1 += sacc[j][3];
        }
        s0 += __shfl_xor_sync(0xffffffffu, s0, 1);
        s0 += __shfl_xor_sync(0xffffffffu, s0, 2);
        s1 += __shfl_xor_sync(0xffffffffu, s1, 1);
        s1 += __shfl_xor_sync(0xffffffffu, s1, 2);
        l0 = l0 * c0 + s0;
        l1 = l1 * c1 + s1;
#pragma unroll
        for (int j = 0; j < 8; j++) {
            o[j][0] *= c0; o[j][1] *= c0; o[j][2] *= c1; o[j][3] *= c1;
        }

        // ---- O += P V (V already visible from barrier (C)) ----
#pragma unroll
        for (int kk = 0; kk < 4; kk++) {
            uint32_t ph[4], pl[4];
#pragma unroll
            for (int half = 0; half < 2; half++) {
                const int jt = 2 * kk + half;
                split2(sacc[jt][0], sacc[jt][1], ph[2*half + 0], pl[2*half + 0]);
                split2(sacc[jt][2], sacc[jt][3], ph[2*half + 1], pl[2*half + 1]);
            }
#pragma unroll
            for (int jp = 0; jp < 4; jp++) {
                const uint32_t va = vbuf + (uint32_t)(kk * 16 + v_row) * KVP
                                  + (uint32_t)(jp * 32) + v_cb;
                uint32_t vh0, vh1, vh2, vh3, vl0, vl1, vl2, vl3;
                ldsm4t(vh0, vh1, vh2, vh3, va);
                ldsm4t(vl0, vl1, vl2, vl3, va + 9216);
                float* o0 = o[2*jp];
                float* o1 = o[2*jp+1];
                mma_bf16(o0[0], o0[1], o0[2], o0[3], ph[0], ph[1], ph[2], ph[3], vh0, vh1);
                mma_bf16(o1[0], o1[1], o1[2], o1[3], ph[0], ph[1], ph[2], ph[3], vh2, vh3);
                mma_bf16(o0[0], o0[1], o0[2], o0[3], ph[0], ph[1], ph[2], ph[3], vl0, vl1);
                mma_bf16(o1[0], o1[1], o1[2], o1[3], ph[0], ph[1], ph[2], ph[3], vl2, vl3);
                mma_bf16(o0[0], o0[1], o0[2], o0[3], pl[0], pl[1], pl[2], pl[3], vh0, vh1);
                mma_bf16(o1[0], o1[1], o1[2], o1[3], pl[0], pl[1], pl[2], pl[3], vh2, vh3);
            }
        }
    }

    // ---- normalize and write split bf16 hi/lo ----
    {
        const float inv0 = 1.f / l0, inv1 = 1.f / l1;
        const int gr0 = q0 + w * 16 + (lane >> 2);
        const size_t row0 = (size_t)(gr0 * B_ + b) * E_;
        const size_t row1 = (size_t)((gr0 + 8) * B_ + b) * E_;
#pragma unroll
        for (int j = 0; j < 8; j++) {
            const int c = h * D_ + j * 8 + (lane & 3) * 2;
            uint32_t h0, l0v, h1, l1v;
            split2(o[j][0] * inv0, o[j][1] * inv0, h0, l0v);
            split2(o[j][2] * inv1, o[j][3] * inv1, h1, l1v);
            *(uint32_t*)(g_atth + row0 + c) = h0;
            *(uint32_t*)(g_attl + row0 + c) = l0v;
            *(uint32_t*)(g_atth + row1 + c) = h1;
            *(uint32_t*)(g_attl + row1 + c) = l1v;
        }
    }
}

// ---------------- launch ----------------
extern "C" void kernel_launch(void* const* d_in, const int* in_sizes, int n_in,
                              void* d_out, int out_size)
{
    const float*         x         = (const float*)d_in[0];
    const void*          edge      = d_in[1];
    const float*         attn_mask = (const float*)d_in[2];
    const unsigned char* kpm       = (const unsigned char*)d_in[3];
    const float*         in_w      = (const float*)d_in[4];
    const float*         in_b      = (const float*)d_in[5];
    const float*         out_w     = (const float*)d_in[6];
    const float*         out_b     = (const float*)d_in[7];
    const float*         edge_tab  = (const float*)d_in[8];
    float* out = (float*)d_out;

    __nv_bfloat16 *xh, *xl, *iwh, *iwl, *owh, *owl, *qkvh, *qkvl, *atth, *attl;
    cudaGetSymbolAddress((void**)&xh,   g_xh);
    cudaGetSymbolAddress((void**)&xl,   g_xl);
    cudaGetSymbolAddress((void**)&iwh,  g_iwh);
    cudaGetSymbolAddress((void**)&iwl,  g_iwl);
    cudaGetSymbolAddress((void**)&owh,  g_owh);
    cudaGetSymbolAddress((void**)&owl,  g_owl);
    cudaGetSymbolAddress((void**)&qkvh, g_qkvh);
    cudaGetSymbolAddress((void**)&qkvl, g_qkvl);
    cudaGetSymbolAddress((void**)&atth, g_atth);
    cudaGetSymbolAddress((void**)&attl, g_attl);

    cudaFuncSetAttribute(gemm_bf16, cudaFuncAttributeMaxDynamicSharedMemorySize, GEMM_SMEM);
    cudaFuncSetAttribute(attn_hmma, cudaFuncAttributeMaxDynamicSharedMemorySize, ATTN_SMEM);

    detect_edge_dtype_kernel<<<1, 32>>>((const unsigned int*)edge);   // also zeroes g_mask_nz
    scan_mask_kernel<<<(L_ * L_) / (256 * 8), 256>>>(attn_mask);
    pack_edge_kernel<<<(B_ * L_ * L_) / (256 * 4), 256>>>(edge);

    split_kernel<<<(ROWS_ * E_ / 4 + 255) / 256, 256>>>(x, xh, xl, ROWS_ * E_ / 4);
    split_kernel<<<(QKV_LD * E_ / 4 + 255) / 256, 256>>>(in_w, iwh, iwl, QKV_LD * E_ / 4);
    split_kernel<<<(E_ * E_ / 4 + 255) / 256, 256>>>(out_w, owh, owl, E_ * E_ / 4);

    gemm_bf16<<<dim3(QKV_LD / 128, ROWS_ / 128), 256, GEMM_SMEM>>>(
        xh, xl, iwh, iwl, in_b, nullptr, qkvh, qkvl, QKV_LD, E_, 1);

    attn_hmma<<<dim3(L_ / 128, B_ * H_), 256, ATTN_SMEM>>>(attn_mask, kpm, edge_tab);

    gemm_bf16<<<dim3(E_ / 128, ROWS_ / 128), 256, GEMM_SMEM>>>(
        atth, attl, owh, owl, out_b, out, nullptr, nullptr, E_, E_, 0);
}

// round 17
// speedup vs baseline: 1.0087x; 1.0087x over previous
#include <cuda_runtime.h>
#include <cuda_bf16.h>
#include <cstdint>

#define L_ 1024
#define B_ 8
#define E_ 512
#define H_ 8
#define D_ 64
#define ROWS_ (L_*B_)          /* 8192 */
#define QKV_LD (3*E_)          /* 1536 */

// ---------------- scratch (no cudaMalloc allowed) ----------------
__device__ __nv_bfloat16 g_qkvh[(size_t)ROWS_ * QKV_LD];
__device__ __nv_bfloat16 g_qkvl[(size_t)ROWS_ * QKV_LD];
__device__ __nv_bfloat16 g_atth[(size_t)ROWS_ * E_];
__device__ __nv_bfloat16 g_attl[(size_t)ROWS_ * E_];
__device__ __nv_bfloat16 g_xh[(size_t)ROWS_ * E_];
__device__ __nv_bfloat16 g_xl[(size_t)ROWS_ * E_];
__device__ __nv_bfloat16 g_iwh[(size_t)QKV_LD * E_];
__device__ __nv_bfloat16 g_iwl[(size_t)QKV_LD * E_];
__device__ __nv_bfloat16 g_owh[(size_t)E_ * E_];
__device__ __nv_bfloat16 g_owl[(size_t)E_ * E_];
__device__ unsigned char g_edge8[(size_t)B_ * L_ * L_];
__device__ int g_is64;
__device__ int g_mask_nz;

// ================= helpers (plain sm_103-safe) =================
__device__ __forceinline__ uint32_t cvta_smem(const void* p) {
    uint32_t a;
    asm("{ .reg .u64 t; cvta.to.shared.u64 t, %1; cvt.u32.u64 %0, t; }" : "=r"(a) : "l"(p));
    return a;
}
__device__ __forceinline__ void ldsm4(uint32_t& r0, uint32_t& r1, uint32_t& r2, uint32_t& r3, uint32_t a) {
    asm volatile("ldmatrix.sync.aligned.m8n8.x4.shared.b16 {%0,%1,%2,%3}, [%4];"
                 : "=r"(r0), "=r"(r1), "=r"(r2), "=r"(r3) : "r"(a));
}
__device__ __forceinline__ void ldsm4t(uint32_t& r0, uint32_t& r1, uint32_t& r2, uint32_t& r3, uint32_t a) {
    asm volatile("ldmatrix.sync.aligned.m8n8.x4.trans.shared.b16 {%0,%1,%2,%3}, [%4];"
                 : "=r"(r0), "=r"(r1), "=r"(r2), "=r"(r3) : "r"(a));
}
__device__ __forceinline__ void mma_bf16(float& d0, float& d1, float& d2, float& d3,
                                         uint32_t a0, uint32_t a1, uint32_t a2, uint32_t a3,
                                         uint32_t b0, uint32_t b1) {
    asm volatile("mma.sync.aligned.m16n8k16.row.col.f32.bf16.bf16.f32 "
                 "{%0,%1,%2,%3}, {%4,%5,%6,%7}, {%8,%9}, {%0,%1,%2,%3};"
                 : "+f"(d0), "+f"(d1), "+f"(d2), "+f"(d3)
                 : "r"(a0), "r"(a1), "r"(a2), "r"(a3), "r"(b0), "r"(b1));
}
#define CP_ASYNC16(dst, src) \
    asm volatile("cp.async.cg.shared.global [%0], [%1], 16;" :: "r"((uint32_t)(dst)), "l"(src))
#define CP_COMMIT() asm volatile("cp.async.commit_group;" ::: "memory")
#define CP_WAIT0()  asm volatile("cp.async.wait_group 0;" ::: "memory")
#define CP_WAIT1()  asm volatile("cp.async.wait_group 1;" ::: "memory")

// fast fp32-pair -> packed bf16x2 (RN, identical numerics to __float2bfloat16)
__device__ __forceinline__ uint32_t cvt_bf16x2(float lo, float hi) {
    uint32_t r;
    asm("cvt.rn.bf16x2.f32 %0, %1, %2;" : "=r"(r) : "f"(hi), "f"(lo));
    return r;
}
__device__ __forceinline__ void split2(float x, float y, uint32_t& hi, uint32_t& lo) {
    hi = cvt_bf16x2(x, y);
    const float xr = __uint_as_float(hi << 16);
    const float yr = __uint_as_float(hi & 0xFFFF0000u);
    lo = cvt_bf16x2(x - xr, y - yr);
}
__device__ __forceinline__ void split4(const float4 v, uint2& hi, uint2& lo) {
    split2(v.x, v.y, hi.x, lo.x);
    split2(v.z, v.w, hi.y, lo.y);
}

// ---------------- detect edge dtype + zero mask flag ----------------
__global__ void detect_edge_dtype_kernel(const unsigned int* __restrict__ e)
{
    const int t = threadIdx.x;
    unsigned v = 0;
    for (int i = t; i < 512; i += 32) v |= e[2 * i + 1];
    const unsigned any = __ballot_sync(0xffffffffu, v != 0u);
    if (t == 0) { g_is64 = (any == 0u) ? 1 : 0; g_mask_nz = 0; }
}

// ---------------- scan attn_mask for any nonzero ----------------
__global__ __launch_bounds__(256) void scan_mask_kernel(const float* __restrict__ m)
{
    const int i = (blockIdx.x * 256 + threadIdx.x) * 8;
    const uint4 a = *(const uint4*)(m + i);
    const uint4 b = *(const uint4*)(m + i + 4);
    const unsigned v = a.x | a.y | a.z | a.w | b.x | b.y | b.z | b.w;
    const unsigned any = __ballot_sync(0xffffffffu, v != 0u);
    if ((threadIdx.x & 31) == 0 && any) atomicOr(&g_mask_nz, 1);
}

// ---------------- pack edge (int32 or int64) -> uint8 ----------------
__global__ __launch_bounds__(256) void pack_edge_kernel(const void* __restrict__ edge)
{
    const int i = blockIdx.x * blockDim.x + threadIdx.x;
    uchar4 u;
    if (g_is64) {
        const long long* e = (const long long*)edge;
        u.x = (unsigned char)e[(size_t)i*4 + 0];
        u.y = (unsigned char)e[(size_t)i*4 + 1];
        u.z = (unsigned char)e[(size_t)i*4 + 2];
        u.w = (unsigned char)e[(size_t)i*4 + 3];
    } else {
        const int4 v = *(const int4*)((const int*)edge + (size_t)i*4);
        u.x = (unsigned char)v.x; u.y = (unsigned char)v.y;
        u.z = (unsigned char)v.z; u.w = (unsigned char)v.w;
    }
    *(uchar4*)(g_edge8 + (size_t)i*4) = u;
}

// ---------------- fp32 -> bf16 hi/lo splitter ----------------
__global__ __launch_bounds__(256) void split_kernel(
    const float* __restrict__ src, __nv_bfloat16* __restrict__ hi,
    __nv_bfloat16* __restrict__ lo, int n4)
{
    const int i = blockIdx.x * blockDim.x + threadIdx.x;
    if (i >= n4) return;
    uint2 h, l;
    split4(*(const float4*)(src + (size_t)i * 4), h, l);
    *(uint2*)(hi + (size_t)i * 4) = h;
    *(uint2*)(lo + (size_t)i * 4) = l;
}

// ================= HMMA GEMM (unchanged from R9) =================
#define GP 40
#define GTILE (128*GP*2)
#define GSTG  (4*GTILE)
#define GEMM_SMEM (2*GSTG)

__global__ __launch_bounds__(256, 2) void gemm_bf16(
    const __nv_bfloat16* __restrict__ Ah, const __nv_bfloat16* __restrict__ Al,
    const __nv_bfloat16* __restrict__ Bh, const __nv_bfloat16* __restrict__ Bl,
    const float* __restrict__ bias,
    float* __restrict__ Cf, __nv_bfloat16* __restrict__ Ch, __nv_bfloat16* __restrict__ Cl,
    int N, int K, int split_out)
{
    extern __shared__ char smc[];
    const uint32_t sb = cvta_smem(smc);
    const int t = threadIdx.x, wid = t >> 5, lane = t & 31;
    const int wm = wid & 3, wn = wid >> 2;
    const int bm = blockIdx.y << 7, bn = blockIdx.x << 7;

    const int r = t >> 1, half = t & 1;
    const __nv_bfloat16* a_h = Ah + (size_t)(bm + r) * K + half * 16;
    const __nv_bfloat16* a_l = Al + (size_t)(bm + r) * K + half * 16;
    const __nv_bfloat16* b_h = Bh + (size_t)(bn + r) * K + half * 16;
    const __nv_bfloat16* b_l = Bl + (size_t)(bn + r) * K + half * 16;
    const uint32_t dstb = (uint32_t)(r * (GP*2) + half * 32);

    const int niter = K >> 5;
#pragma unroll
    for (int p = 0; p < 2; p++) {
        const uint32_t d = sb + p * GSTG + dstb;
        const int ko = p * 32;
        CP_ASYNC16(d,             a_h + ko); CP_ASYNC16(d + 16,             a_h + ko + 8);
        CP_ASYNC16(d + GTILE,     a_l + ko); CP_ASYNC16(d + GTILE + 16,     a_l + ko + 8);
        CP_ASYNC16(d + 2*GTILE,   b_h + ko); CP_ASYNC16(d + 2*GTILE + 16,   b_h + ko + 8);
        CP_ASYNC16(d + 3*GTILE,   b_l + ko); CP_ASYNC16(d + 3*GTILE + 16,   b_l + ko + 8);
        CP_COMMIT();
    }

    float acc[2][8][4];
#pragma unroll
    for (int i = 0; i < 2; i++)
#pragma unroll
        for (int j = 0; j < 8; j++)
#pragma unroll
            for (int c = 0; c < 4; c++) acc[i][j][c] = 0.f;

    const uint32_t a_row = (uint32_t)((lane & 7) + ((lane >> 3) & 1) * 8);
    const uint32_t a_kb  = (uint32_t)((lane >> 4) << 4);
    const uint32_t p_row = (uint32_t)((lane & 7) + ((lane >> 4) & 1) * 8);
    const uint32_t p_kb  = (uint32_t)(((lane >> 3) & 1) << 4);

    for (int it = 0; it < niter; it++) {
        if (it == niter - 1) { CP_WAIT0(); } else { CP_WAIT1(); }
        __syncthreads();
        const uint32_t s = sb + (uint32_t)((it & 1) * GSTG);
#pragma unroll
        for (int kk = 0; kk < 2; kk++) {
            uint32_t ah[2][4], al[2][4];
#pragma unroll
            for (int i = 0; i < 2; i++) {
                const uint32_t ad = s + (uint32_t)(wm * 32 + i * 16 + a_row) * (GP*2)
                                  + (uint32_t)(kk * 32) + a_kb;
                ldsm4(ah[i][0], ah[i][1], ah[i][2], ah[i][3], ad);
                ldsm4(al[i][0], al[i][1], al[i][2], al[i][3], ad + GTILE);
            }
#pragma unroll
            for (int jp = 0; jp < 4; jp++) {
                const uint32_t bd = s + 2*GTILE + (uint32_t)(wn * 64 + jp * 16 + p_row) * (GP*2)
                                  + (uint32_t)(kk * 32) + p_kb;
                uint32_t bh0, bh1, bh2, bh3, bl0, bl1, bl2, bl3;
                ldsm4(bh0, bh1, bh2, bh3, bd);
                ldsm4(bl0, bl1, bl2, bl3, bd + GTILE);
                float* x00 = acc[0][2*jp]; float* x01 = acc[0][2*jp+1];
                float* x10 = acc[1][2*jp]; float* x11 = acc[1][2*jp+1];
                mma_bf16(x00[0], x00[1], x00[2], x00[3], ah[0][0], ah[0][1], ah[0][2], ah[0][3], bh0, bh1);
                mma_bf16(x01[0], x01[1], x01[2], x01[3], ah[0][0], ah[0][1], ah[0][2], ah[0][3], bh2, bh3);
                mma_bf16(x10[0], x10[1], x10[2], x10[3], ah[1][0], ah[1][1], ah[1][2], ah[1][3], bh0, bh1);
                mma_bf16(x11[0], x11[1], x11[2], x11[3], ah[1][0], ah[1][1], ah[1][2], ah[1][3], bh2, bh3);
                mma_bf16(x00[0], x00[1], x00[2], x00[3], ah[0][0], ah[0][1], ah[0][2], ah[0][3], bl0, bl1);
                mma_bf16(x01[0], x01[1], x01[2], x01[3], ah[0][0], ah[0][1], ah[0][2], ah[0][3], bl2, bl3);
                mma_bf16(x10[0], x10[1], x10[2], x10[3], ah[1][0], ah[1][1], ah[1][2], ah[1][3], bl0, bl1);
                mma_bf16(x11[0], x11[1], x11[2], x11[3], ah[1][0], ah[1][1], ah[1][2], ah[1][3], bl2, bl3);
                mma_bf16(x00[0], x00[1], x00[2], x00[3], al[0][0], al[0][1], al[0][2], al[0][3], bh0, bh1);
                mma_bf16(x01[0], x01[1], x01[2], x01[3], al[0][0], al[0][1], al[0][2], al[0][3], bh2, bh3);
                mma_bf16(x10[0], x10[1], x10[2], x10[3], al[1][0], al[1][1], al[1][2], al[1][3], bh0, bh1);
                mma_bf16(x11[0], x11[1], x11[2], x11[3], al[1][0], al[1][1], al[1][2], al[1][3], bh2, bh3);
            }
        }
        __syncthreads();
        if (it + 2 < niter) {
            const uint32_t d = sb + ((it + 2) & 1) * GSTG + dstb;
            const int ko = (it + 2) * 32;
            CP_ASYNC16(d,             a_h + ko); CP_ASYNC16(d + 16,             a_h + ko + 8);
            CP_ASYNC16(d + GTILE,     a_l + ko); CP_ASYNC16(d + GTILE + 16,     a_l + ko + 8);
            CP_ASYNC16(d + 2*GTILE,   b_h + ko); CP_ASYNC16(d + 2*GTILE + 16,   b_h + ko + 8);
            CP_ASYNC16(d + 3*GTILE,   b_l + ko); CP_ASYNC16(d + 3*GTILE + 16,   b_l + ko + 8);
            CP_COMMIT();
        }
    }

#pragma unroll
    for (int i = 0; i < 2; i++) {
        const int r0 = bm + wm * 32 + i * 16 + (lane >> 2);
#pragma unroll
        for (int j = 0; j < 8; j++) {
            const int c = bn + wn * 64 + j * 8 + (lane & 3) * 2;
            const float2 b2 = *(const float2*)(bias + c);
            const float v00 = acc[i][j][0] + b2.x, v01 = acc[i][j][1] + b2.y;
            const float v10 = acc[i][j][2] + b2.x, v11 = acc[i][j][3] + b2.y;
            if (split_out) {
                uint32_t h0, l0v, h1, l1v;
                split2(v00, v01, h0, l0v);
                split2(v10, v11, h1, l1v);
                *(uint32_t*)(Ch + (size_t)r0 * N + c)       = h0;
                *(uint32_t*)(Cl + (size_t)r0 * N + c)       = l0v;
                *(uint32_t*)(Ch + (size_t)(r0 + 8) * N + c) = h1;
                *(uint32_t*)(Cl + (size_t)(r0 + 8) * N + c) = l1v;
            } else {
                float2 o0 = { v00, v01 }, o1 = { v10, v11 };
                *(float2*)(Cf + (size_t)r0 * N + c)       = o0;
                *(float2*)(Cf + (size_t)(r0 + 8) * N + c) = o1;
            }
        }
    }
}

// ================= HMMA fused flash attention (all tiles double-buffered) =================
// grid (8, 64), 256 thr = 8 warps. K, V, edge double-buffered, one commit
// group per iteration (prefetch distance 1), 2 barriers/iter, no mid waits.
// Mask: skipped entirely when g_mask_nz == 0 (direct-LDG slow path otherwise).
#define KVP 144                          /* bytes per K/V row (72 bf16) */
#define KBUF 18432                       /* per K or V buffer (hi+lo) */
#define K0_OFF 0
#define K1_OFF 18432
#define V0_OFF 36864
#define V1_OFF 55296
#define EDGEP 80
#define E0_OFF 73728                     /* 128*80 = 10240 per buffer */
#define E1_OFF 83968
#define KPS_OFF 94208
#define ATTN_SMEM (KPS_OFF + 4096 + 64)  /* ~98.4 KB -> 2 CTAs/SM */

__global__ __launch_bounds__(256, 2) void attn_hmma(
    const float* __restrict__ attn_mask,
    const unsigned char* __restrict__ kpm,
    const float* __restrict__ edge_tab)
{
    extern __shared__ char smc[];
    const uint32_t sb = cvta_smem(smc);

    const int t = threadIdx.x, w = t >> 5, lane = t & 31;
    const int qb = blockIdx.x, bh = blockIdx.y;
    const int b = bh >> 3, h = bh & 7;
    const int q0 = qb << 7;
    const size_t edge_base = (size_t)b << 20;
    const int mnz = g_mask_nz;

    const float etreg = edge_tab[(lane & 15) * H_ + h];

    const uint32_t a_row = (uint32_t)((lane & 7) + ((lane >> 3) & 1) * 8);
    const uint32_t a_kb  = (uint32_t)((lane >> 4) << 4);
    const uint32_t p_row = (uint32_t)((lane & 7) + ((lane >> 4) & 1) * 8);
    const uint32_t p_kb  = (uint32_t)(((lane >> 3) & 1) << 4);
    const uint32_t v_row = (uint32_t)(lane & 15);
    const uint32_t v_cb  = (uint32_t)((lane >> 4) << 4);

    const int kv_r = t >> 2, kv_q4 = t & 3;
    const uint32_t kv_d = (uint32_t)(kv_r * KVP + kv_q4 * 32);
    const int me_i = t >> 1, me_half = t & 1;

    // ---- prologue: kps table + Q staging (through K0/K1 regions) ----
    {
        const uchar4 kc = *(const uchar4*)(kpm + b * L_ + t * 4);
        float4 kf;
        kf.x = kc.x ? -1e30f : 0.f; kf.y = kc.y ? -1e30f : 0.f;
        kf.z = kc.z ? -1e30f : 0.f; kf.w = kc.w ? -1e30f : 0.f;
        *(float4*)(smc + KPS_OFF + t * 16) = kf;
    }
    {
        const __nv_bfloat16* qh = g_qkvh + (size_t)((q0 + me_i) * B_ + b) * QKV_LD + h * D_ + me_half * 32;
        const __nv_bfloat16* ql = g_qkvl + (size_t)((q0 + me_i) * B_ + b) * QKV_LD + h * D_ + me_half * 32;
        const uint32_t d = sb + (uint32_t)(me_i * KVP + me_half * 64);
#pragma unroll
        for (int g = 0; g < 4; g++) {
            CP_ASYNC16(d + g * 16,          qh + g * 8);
            CP_ASYNC16(d + K1_OFF + g * 16, ql + g * 8);
        }
        CP_COMMIT();
        CP_WAIT0();
    }
    __syncthreads();
    uint32_t qfh[4][4], qfl[4][4];
#pragma unroll
    for (int kk = 0; kk < 4; kk++) {
        const uint32_t qa = sb + (uint32_t)(w * 16 + a_row) * KVP + (uint32_t)(kk * 32) + a_kb;
        ldsm4(qfh[kk][0], qfh[kk][1], qfh[kk][2], qfh[kk][3], qa);
        ldsm4(qfl[kk][0], qfl[kk][1], qfl[kk][2], qfl[kk][3], qa + K1_OFF);
    }
    __syncthreads();   // all warps done reading Q region before K/V overwrite

    // issue group(0): K(0), V(0), edge(0) into buffers 0
    {
        const size_t rowb = (size_t)((0 + kv_r) * B_ + b) * QKV_LD + h * D_;
        const __nv_bfloat16* kh = g_qkvh + rowb + E_   + kv_q4 * 16;
        const __nv_bfloat16* kl = g_qkvl + rowb + E_   + kv_q4 * 16;
        const __nv_bfloat16* vh = g_qkvh + rowb + 2*E_ + kv_q4 * 16;
        const __nv_bfloat16* vl = g_qkvl + rowb + 2*E_ + kv_q4 * 16;
        const uint32_t dk = sb + K0_OFF + kv_d;
        const uint32_t dv = sb + V0_OFF + kv_d;
        CP_ASYNC16(dk,        kh); CP_ASYNC16(dk + 16,        kh + 8);
        CP_ASYNC16(dk + 9216, kl); CP_ASYNC16(dk + 9216 + 16, kl + 8);
        CP_ASYNC16(dv,        vh); CP_ASYNC16(dv + 16,        vh + 8);
        CP_ASYNC16(dv + 9216, vl); CP_ASYNC16(dv + 9216 + 16, vl + 8);
        const unsigned char* esrc = g_edge8 + edge_base + (size_t)(q0 + me_i) * L_ + me_half * 32;
        const uint32_t ed = sb + E0_OFF + (uint32_t)(me_i * EDGEP + me_half * 32);
        CP_ASYNC16(ed, esrc); CP_ASYNC16(ed + 16, esrc + 16);
        CP_COMMIT();
    }

    float o[8][4];
#pragma unroll
    for (int j = 0; j < 8; j++)
#pragma unroll
        for (int c = 0; c < 4; c++) o[j][c] = 0.f;
    float m0p = -1e30f, m1p = -1e30f, l0 = 0.f, l1 = 0.f;

    for (int kb = 0; kb < 16; kb++) {
        const int m0 = kb << 6;
        if (kb) __syncthreads();   // (A) all warps done with buffers we overwrite next

        // ---- issue group(kb+1) into alt buffers ----
        if (kb + 1 < 16) {
            const int alt = (kb + 1) & 1;
            const size_t rowb = (size_t)(((m0 + 64) + kv_r) * B_ + b) * QKV_LD + h * D_;
            const __nv_bfloat16* kh = g_qkvh + rowb + E_   + kv_q4 * 16;
            const __nv_bfloat16* kl = g_qkvl + rowb + E_   + kv_q4 * 16;
            const __nv_bfloat16* vh = g_qkvh + rowb + 2*E_ + kv_q4 * 16;
            const __nv_bfloat16* vl = g_qkvl + rowb + 2*E_ + kv_q4 * 16;
            const uint32_t dk = sb + (uint32_t)(alt ? K1_OFF : K0_OFF) + kv_d;
            const uint32_t dv = sb + (uint32_t)(alt ? V1_OFF : V0_OFF) + kv_d;
            CP_ASYNC16(dk,        kh); CP_ASYNC16(dk + 16,        kh + 8);
            CP_ASYNC16(dk + 9216, kl); CP_ASYNC16(dk + 9216 + 16, kl + 8);
            CP_ASYNC16(dv,        vh); CP_ASYNC16(dv + 16,        vh + 8);
            CP_ASYNC16(dv + 9216, vl); CP_ASYNC16(dv + 9216 + 16, vl + 8);
            const unsigned char* esrc = g_edge8 + edge_base + (size_t)(q0 + me_i) * L_ + (m0 + 64) + me_half * 32;
            const uint32_t ed = sb + (uint32_t)(alt ? E1_OFF : E0_OFF) + (uint32_t)(me_i * EDGEP + me_half * 32);
            CP_ASYNC16(ed, esrc); CP_ASYNC16(ed + 16, esrc + 16);
            CP_COMMIT();
            CP_WAIT1();            // group(kb) complete
        } else {
            CP_WAIT0();
        }
        __syncthreads();           // (C) group(kb) visible to all warps

        const int cur = kb & 1;
        const uint32_t kbuf = sb + (uint32_t)(cur ? K1_OFF : K0_OFF);
        const uint32_t vbuf = sb + (uint32_t)(cur ? V1_OFF : V0_OFF);
        const uint32_t ebuf = (uint32_t)(cur ? E1_OFF : E0_OFF);

        // ---- S = Q K^T (16 x 64 per warp), 3 products, interleaved ----
        float sacc[8][4];
#pragma unroll
        for (int j = 0; j < 8; j++)
#pragma unroll
            for (int c = 0; c < 4; c++) sacc[j][c] = 0.f;
#pragma unroll
        for (int kk = 0; kk < 4; kk++) {
#pragma unroll
            for (int jp = 0; jp < 4; jp++) {
                const uint32_t ka = kbuf + (uint32_t)(jp * 16 + p_row) * KVP
                                  + (uint32_t)(kk * 32) + p_kb;
                uint32_t kh0, kh1, kh2, kh3, kl0, kl1, kl2, kl3;
                ldsm4(kh0, kh1, kh2, kh3, ka);
                ldsm4(kl0, kl1, kl2, kl3, ka + 9216);
                float* s0 = sacc[2*jp];
                float* s1 = sacc[2*jp+1];
                mma_bf16(s0[0], s0[1], s0[2], s0[3], qfh[kk][0], qfh[kk][1], qfh[kk][2], qfh[kk][3], kh0, kh1);
                mma_bf16(s1[0], s1[1], s1[2], s1[3], qfh[kk][0], qfh[kk][1], qfh[kk][2], qfh[kk][3], kh2, kh3);
                mma_bf16(s0[0], s0[1], s0[2], s0[3], qfh[kk][0], qfh[kk][1], qfh[kk][2], qfh[kk][3], kl0, kl1);
                mma_bf16(s1[0], s1[1], s1[2], s1[3], qfh[kk][0], qfh[kk][1], qfh[kk][2], qfh[kk][3], kl2, kl3);
                mma_bf16(s0[0], s0[1], s0[2], s0[3], qfl[kk][0], qfl[kk][1], qfl[kk][2], qfl[kk][3], kh0, kh1);
                mma_bf16(s1[0], s1[1], s1[2], s1[3], qfl[kk][0], qfl[kk][1], qfl[kk][2], qfl[kk][3], kh2, kh3);
            }
        }

        // ---- S epilogue: scale + edge(shfl) + kps (+ mask LDG slow path) ----
        {
            const int rl = w * 16 + (lane >> 2);
            const uint32_t erow0 = ebuf + (uint32_t)(rl * EDGEP);
#pragma unroll
            for (int j = 0; j < 8; j++) {
                const int c = j * 8 + (lane & 3) * 2;
                const float2 kp = *(const float2*)(smc + KPS_OFF + (m0 + c) * 4);
                const unsigned short e0 = *(const unsigned short*)(smc + erow0 + c);
                const unsigned short e1 = *(const unsigned short*)(smc + erow0 + 8 * EDGEP + c);
                const float ev00 = __shfl_sync(0xffffffffu, etreg, e0 & 15);
                const float ev01 = __shfl_sync(0xffffffffu, etreg, (e0 >> 8) & 15);
                const float ev10 = __shfl_sync(0xffffffffu, etreg, e1 & 15);
                const float ev11 = __shfl_sync(0xffffffffu, etreg, (e1 >> 8) & 15);
                float mk00 = 0.f, mk01 = 0.f, mk10 = 0.f, mk11 = 0.f;
                if (mnz) {   // slow path: direct LDG of mask (L2-cached)
                    const float2 m0v = *(const float2*)(attn_mask + (size_t)(q0 + rl) * L_ + m0 + c);
                    const float2 m1v = *(const float2*)(attn_mask + (size_t)(q0 + rl + 8) * L_ + m0 + c);
                    mk00 = m0v.x; mk01 = m0v.y; mk10 = m1v.x; mk11 = m1v.y;
                }
                sacc[j][0] = sacc[j][0] * 0.125f + mk00 + ev00 + kp.x;
                sacc[j][1] = sacc[j][1] * 0.125f + mk01 + ev01 + kp.y;
                sacc[j][2] = sacc[j][2] * 0.125f + mk10 + ev10 + kp.x;
                sacc[j][3] = sacc[j][3] * 0.125f + mk11 + ev11 + kp.y;
            }
        }

        // ---- online softmax ----
        float mx0 = -1e30f, mx1 = -1e30f;
#pragma unroll
        for (int j = 0; j < 8; j++) {
            mx0 = fmaxf(mx0, fmaxf(sacc[j][0], sacc[j][1]));
            mx1 = fmaxf(mx1, fmaxf(sacc[j][2], sacc[j][3]));
        }
        mx0 = fmaxf(mx0, __shfl_xor_sync(0xffffffffu, mx0, 1));
        mx0 = fmaxf(mx0, __shfl_xor_sync(0xffffffffu, mx0, 2));
        mx1 = fmaxf(mx1, __shfl_xor_sync(0xffffffffu, mx1, 1));
        mx1 = fmaxf(mx1, __shfl_xor_sync(0xffffffffu, mx1, 2));
        const float mn0 = fmaxf(m0p, mx0), mn1 = fmaxf(m1p, mx1);
        const float c0 = __expf(m0p - mn0), c1 = __expf(m1p - mn1);
        m0p = mn0; m1p = mn1;
        float s0 = 0.f, s1 = 0.f;
#pragma unroll
        for (int j = 0; j < 8; j++) {
            sacc[j][0] = __expf(sacc[j][0] - mn0); s0 += sacc[j][0];
            sacc[j][1] = __expf(sacc[j][1] - mn0); s0 += sacc[j][1];
            sacc[j][2] = __expf(sacc[j][2] - mn1); s1 += sacc[j][2];
            sacc[j][3] = __expf(sacc[j][3] - mn1); s1 += sacc[j][3];
        }
        s0 += __shfl_xor_sync(0xffffffffu, s0, 1);
        s0 += __shfl_xor_sync(0xffffffffu, s0, 2);
        s1 += __shfl_xor_sync(0xffffffffu, s1, 1);
        s1 += __shfl_xor_sync(0xffffffffu, s1, 2);
        l0 = l0 * c0 + s0;
        l1 = l1 * c1 + s1;
#pragma unroll
        for (int j = 0; j < 8; j++) {
            o[j][0] *= c0; o[j][1] *= c0; o[j][2] *= c1; o[j][3] *= c1;
        }

        // ---- O += P V (V already visible from barrier (C)) ----
#pragma unroll
        for (int kk = 0; kk < 4; kk++) {
            uint32_t ph[4], pl[4];
#pragma unroll
            for (int half = 0; half < 2; half++) {
                const int jt = 2 * kk + half;
                split2(sacc[jt][0], sacc[jt][1], ph[2*half + 0], pl[2*half + 0]);
                split2(sacc[jt][2], sacc[jt][3], ph[2*half + 1], pl[2*half + 1]);
            }
#pragma unroll
            for (int jp = 0; jp < 4; jp++) {
                const uint32_t va = vbuf + (uint32_t)(kk * 16 + v_row) * KVP
                                  + (uint32_t)(jp * 32) + v_cb;
                uint32_t vh0, vh1, vh2, vh3, vl0, vl1, vl2, vl3;
                ldsm4t(vh0, vh1, vh2, vh3, va);
                ldsm4t(vl0, vl1, vl2, vl3, va + 9216);
                float* o0 = o[2*jp];
                float* o1 = o[2*jp+1];
                mma_bf16(o0[0], o0[1], o0[2], o0[3], ph[0], ph[1], ph[2], ph[3], vh0, vh1);
                mma_bf16(o1[0], o1[1], o1[2], o1[3], ph[0], ph[1], ph[2], ph[3], vh2, vh3);
                mma_bf16(o0[0], o0[1], o0[2], o0[3], ph[0], ph[1], ph[2], ph[3], vl0, vl1);
                mma_bf16(o1[0], o1[1], o1[2], o1[3], ph[0], ph[1], ph[2], ph[3], vl2, vl3);
                mma_bf16(o0[0], o0[1], o0[2], o0[3], pl[0], pl[1], pl[2], pl[3], vh0, vh1);
                mma_bf16(o1[0], o1[1], o1[2], o1[3], pl[0], pl[1], pl[2], pl[3], vh2, vh3);
            }
        }
    }

    // ---- normalize and write split bf16 hi/lo ----
    {
        const float inv0 = 1.f / l0, inv1 = 1.f / l1;
        const int gr0 = q0 + w * 16 + (lane >> 2);
        const size_t row0 = (size_t)(gr0 * B_ + b) * E_;
        const size_t row1 = (size_t)((gr0 + 8) * B_ + b) * E_;
#pragma unroll
        for (int j = 0; j < 8; j++) {
            const int c = h * D_ + j * 8 + (lane & 3) * 2;
            uint32_t h0, l0v, h1, l1v;
            split2(o[j][0] * inv0, o[j][1] * inv0, h0, l0v);
            split2(o[j][2] * inv1, o[j][3] * inv1, h1, l1v);
            *(uint32_t*)(g_atth + row0 + c) = h0;
            *(uint32_t*)(g_attl + row0 + c) = l0v;
            *(uint32_t*)(g_atth + row1 + c) = h1;
            *(uint32_t*)(g_attl + row1 + c) = l1v;
        }
    }
}

// ---------------- launch ----------------
extern "C" void kernel_launch(void* const* d_in, const int* in_sizes, int n_in,
                              void* d_out, int out_size)
{
    const float*         x         = (const float*)d_in[0];
    const void*          edge      = d_in[1];
    const float*         attn_mask = (const float*)d_in[2];
    const unsigned char* kpm       = (const unsigned char*)d_in[3];
    const float*         in_w      = (const float*)d_in[4];
    const float*         in_b      = (const float*)d_in[5];
    const float*         out_w     = (const float*)d_in[6];
    const float*         out_b     = (const float*)d_in[7];
    const float*         edge_tab  = (const float*)d_in[8];
    float* out = (float*)d_out;

    __nv_bfloat16 *xh, *xl, *iwh, *iwl, *owh, *owl, *qkvh, *qkvl, *atth, *attl;
    cudaGetSymbolAddress((void**)&xh,   g_xh);
    cudaGetSymbolAddress((void**)&xl,   g_xl);
    cudaGetSymbolAddress((void**)&iwh,  g_iwh);
    cudaGetSymbolAddress((void**)&iwl,  g_iwl);
    cudaGetSymbolAddress((void**)&owh,  g_owh);
    cudaGetSymbolAddress((void**)&owl,  g_owl);
    cudaGetSymbolAddress((void**)&qkvh, g_qkvh);
    cudaGetSymbolAddress((void**)&qkvl, g_qkvl);
    cudaGetSymbolAddress((void**)&atth, g_atth);
    cudaGetSymbolAddress((void**)&attl, g_attl);

    cudaFuncSetAttribute(gemm_bf16, cudaFuncAttributeMaxDynamicSharedMemorySize, GEMM_SMEM);
    cudaFuncSetAttribute(attn_hmma, cudaFuncAttributeMaxDynamicSharedMemorySize, ATTN_SMEM);

    detect_edge_dtype_kernel<<<1, 32>>>((const unsigned int*)edge);   // also zeroes g_mask_nz
    scan_mask_kernel<<<(L_ * L_) / (256 * 8), 256>>>(attn_mask);
    pack_edge_kernel<<<(B_ * L_ * L_) / (256 * 4), 256>>>(edge);

    split_kernel<<<(ROWS_ * E_ / 4 + 255) / 256, 256>>>(x, xh, xl, ROWS_ * E_ / 4);
    split_kernel<<<(QKV_LD * E_ / 4 + 255) / 256, 256>>>(in_w, iwh, iwl, QKV_LD * E_ / 4);
    split_kernel<<<(E_ * E_ / 4 + 255) / 256, 256>>>(out_w, owh, owl, E_ * E_ / 4);

    gemm_bf16<<<dim3(QKV_LD / 128, ROWS_ / 128), 256, GEMM_SMEM>>>(
        xh, xl, iwh, iwl, in_b, nullptr, qkvh, qkvl, QKV_LD, E_, 1);

    attn_hmma<<<dim3(L_ / 128, B_ * H_), 256, ATTN_SMEM>>>(attn_mask, kpm, edge_tab);

    gemm_bf16<<<dim3(E_ / 128, ROWS_ / 128), 256, GEMM_SMEM>>>(
        atth, attl, owh, owl, out_b, out, nullptr, nullptr, E_, E_, 0);
}